// round 1
// baseline (speedup 1.0000x reference)
#include <cuda_runtime.h>
#include <cuda_bf16.h>
#include <cstdint>

// out[i,j,:] = W[idx_res] + W[66+idx_tok] + ent*W[132] + W[133+idx_chain]
// Folded smem table S (138 rows x 128 f32):
//   rows   0..64 : W[r]                       (idx_res, same-chain: clamp -> [0,64])
//   rows  65..130: W[66+t] + W[138]           (token table, same-chain chain-bin==5 folded)
//   rows 131..135: W[65] + W[131] + W[133+c]  (diff-chain: res=65, tok=65 folded)
//   row  136     : zeros                      (second operand for diff-chain pairs)
//   row  137     : W[132]                     (entity row, kept in registers)

#define TAB_ROWS 138

__global__ void __launch_bounds__(512, 3)
rpe_kernel(const float* __restrict__ feats, const float* __restrict__ W,
           float* __restrict__ out, int n)
{
    extern __shared__ float smem[];
    float* S = smem;                       // TAB_ROWS*128 floats
    int*   jidx = (int*)(smem + TAB_ROWS * 128);   // n ints

    const int tid = threadIdx.x;
    const int i   = blockIdx.x;

    // ---- Phase 0: build folded table ----
    for (int idx = tid; idx < TAB_ROWS * 128; idx += blockDim.x) {
        int r = idx >> 7;
        int e = idx & 127;
        float v;
        if (r < 65) {
            v = W[r * 128 + e];
        } else if (r < 131) {
            v = W[(66 + (r - 65)) * 128 + e] + W[138 * 128 + e];
        } else if (r < 136) {
            v = W[65 * 128 + e] + W[131 * 128 + e] + W[(133 + (r - 131)) * 128 + e];
        } else if (r == 136) {
            v = 0.0f;
        } else {
            v = W[132 * 128 + e];
        }
        S[idx] = v;
    }

    // ---- Phase 0b: packed per-j indices (a | b<<8 | ent<<16) ----
    const float res_i  = feats[i * 10 + 0];
    const float tok_i  = feats[i * 10 + 1];
    const float asym_i = feats[i * 10 + 2];
    const float ent_i  = feats[i * 10 + 3];
    const float sym_i  = feats[i * 10 + 4];

    for (int j = tid; j < n; j += blockDim.x) {
        const float res_j  = feats[j * 10 + 0];
        const float tok_j  = feats[j * 10 + 1];
        const float asym_j = feats[j * 10 + 2];
        const float ent_j  = feats[j * 10 + 3];
        const float sym_j  = feats[j * 10 + 4];

        int a, b;
        if (asym_i == asym_j) {
            const int dres = (int)(res_i - res_j);
            a = min(max(dres + 32, 0), 64);
            int t;
            if (dres == 0) {
                const int dtok = (int)(tok_i - tok_j);
                t = min(max(dtok + 32, 0), 64);
            } else {
                t = 65;
            }
            b = 65 + t;
        } else {
            const int c = min(max((int)(sym_i - sym_j) + 2, 0), 4);
            a = 131 + c;
            b = 136;                       // zero row
        }
        const int ent = (ent_i == ent_j) ? 1 : 0;
        jidx[j] = a | (b << 8) | (ent << 16);
    }
    __syncthreads();

    // ---- Phase 1: warp-per-pair gather + streaming store ----
    const int e4    = tid & 31;            // float4 column within the 128-dim row
    const int warps = blockDim.x >> 5;
    const float4* __restrict__ S4 = (const float4*)S;

    // entity row held in registers (added rarely, predicated)
    const float4 went = S4[137 * 32 + e4];

    float* __restrict__ out_i = out + ((size_t)i * (size_t)n) * 128;

    for (int j = (tid >> 5); j < n; j += warps) {
        const int p = jidx[j];             // LDS broadcast
        const int a = p & 255;
        const int b = (p >> 8) & 255;

        float4 va = S4[a * 32 + e4];
        float4 vb = S4[b * 32 + e4];
        float4 v;
        v.x = va.x + vb.x;
        v.y = va.y + vb.y;
        v.z = va.z + vb.z;
        v.w = va.w + vb.w;
        if (p >> 16) {
            v.x += went.x; v.y += went.y; v.z += went.z; v.w += went.w;
        }
        // streaming store: output is write-once, don't keep it in L2
        __stcs((float4*)(out_i + (size_t)j * 128) + e4, v);
    }
}

extern "C" void kernel_launch(void* const* d_in, const int* in_sizes, int n_in,
                              void* d_out, int out_size)
{
    const float* feats = (const float*)d_in[0];   // [1, n, 10] f32
    const float* W     = (const float*)d_in[1];   // [139, 128] f32
    float* out         = (float*)d_out;           // [1, n, n, 128] f32

    const int n = in_sizes[0] / 10;               // b == 1

    const int smem_bytes = TAB_ROWS * 128 * (int)sizeof(float) + n * (int)sizeof(int);
    cudaFuncSetAttribute(rpe_kernel, cudaFuncAttributeMaxDynamicSharedMemorySize, smem_bytes);

    rpe_kernel<<<n, 512, smem_bytes>>>(feats, W, out, n);
}

// round 3
// speedup vs baseline: 1.1405x; 1.1405x over previous
#include <cuda_runtime.h>
#include <cuda_bf16.h>
#include <cstdint>

// Single-row fold:
//   same chain, dres!=0 : out = A[clip(dres+32)]      + ent*W[132]
//   same chain, dres==0 : out = B[clip(dtok+32)]      + ent*W[132]
//   diff chain          : out = C[clip(dsym+2,0,4)]   + ent*W[132]
// where
//   A[r] = W[r]   + W[131] + W[138]    rows   0..64   (r never ==32 at use sites)
//   B[t] = W[32]  + W[66+t]+ W[138]    rows  65..129
//   C[c] = W[65]  + W[131] + W[133+c]  rows 130..134
//   row 135 = W[132] (entity row, kept in registers)

#define TAB_ROWS 136

__global__ void __launch_bounds__(512, 3)
rpe_kernel(const float* __restrict__ feats, const float* __restrict__ W,
           float* __restrict__ out, int n)
{
    extern __shared__ float smem[];
    float* S   = smem;                            // TAB_ROWS*128 floats
    int*  jidx = (int*)(smem + TAB_ROWS * 128);   // n ints

    const int tid = threadIdx.x;
    const int i   = blockIdx.x;

    // ---- Phase 0: build folded single-row table ----
    for (int idx = tid; idx < TAB_ROWS * 128; idx += blockDim.x) {
        int r = idx >> 7;
        int e = idx & 127;
        float v;
        if (r < 65) {
            v = W[r * 128 + e] + W[131 * 128 + e] + W[138 * 128 + e];
        } else if (r < 130) {
            v = W[32 * 128 + e] + W[(66 + (r - 65)) * 128 + e] + W[138 * 128 + e];
        } else if (r < 135) {
            v = W[65 * 128 + e] + W[131 * 128 + e] + W[(133 + (r - 130)) * 128 + e];
        } else {
            v = W[132 * 128 + e];
        }
        S[idx] = v;
    }

    // ---- Phase 0b: per-j packed index (row | ent<<8) ----
    const float res_i  = feats[i * 10 + 0];
    const float tok_i  = feats[i * 10 + 1];
    const float asym_i = feats[i * 10 + 2];
    const float ent_i  = feats[i * 10 + 3];
    const float sym_i  = feats[i * 10 + 4];

    for (int j = tid; j < n; j += blockDim.x) {
        const float res_j  = feats[j * 10 + 0];
        const float tok_j  = feats[j * 10 + 1];
        const float asym_j = feats[j * 10 + 2];
        const float ent_j  = feats[j * 10 + 3];
        const float sym_j  = feats[j * 10 + 4];

        int row;
        if (asym_i == asym_j) {
            const int dres = (int)(res_i - res_j);
            if (dres != 0) {
                row = min(max(dres + 32, 0), 64);            // A table
            } else {
                const int dtok = (int)(tok_i - tok_j);
                row = 65 + min(max(dtok + 32, 0), 64);       // B table
            }
        } else {
            row = 130 + min(max((int)(sym_i - sym_j) + 2, 0), 4);  // C table
        }
        const int ent = (ent_i == ent_j) ? 1 : 0;
        jidx[j] = row | (ent << 8);
    }
    __syncthreads();

    // ---- Phase 1: warp-per-pair single-row gather + streaming store ----
    const int e4    = tid & 31;                    // float4 lane within 128-dim row
    const int wid   = tid >> 5;
    const int warps = blockDim.x >> 5;
    const float4* __restrict__ S4 = (const float4*)S;

    const float4 went = S4[135 * 32 + e4];         // entity row in registers

    float* __restrict__ out_i = out + ((size_t)i * (size_t)n) * 128;

    int j = wid;
    // unroll x2 for LDS-latency ILP
    for (; j + warps < n; j += 2 * warps) {
        const int j2 = j + warps;
        const int p0 = jidx[j];
        const int p1 = jidx[j2];
        float4 v0 = S4[(p0 & 255) * 32 + e4];
        float4 v1 = S4[(p1 & 255) * 32 + e4];
        if (p0 >> 8) { v0.x += went.x; v0.y += went.y; v0.z += went.z; v0.w += went.w; }
        if (p1 >> 8) { v1.x += went.x; v1.y += went.y; v1.z += went.z; v1.w += went.w; }
        __stcs((float4*)(out_i + (size_t)j  * 128) + e4, v0);
        __stcs((float4*)(out_i + (size_t)j2 * 128) + e4, v1);
    }
    for (; j < n; j += warps) {
        const int p = jidx[j];
        float4 v = S4[(p & 255) * 32 + e4];
        if (p >> 8) { v.x += went.x; v.y += went.y; v.z += went.z; v.w += went.w; }
        __stcs((float4*)(out_i + (size_t)j * 128) + e4, v);
    }
}

extern "C" void kernel_launch(void* const* d_in, const int* in_sizes, int n_in,
                              void* d_out, int out_size)
{
    const float* feats = (const float*)d_in[0];   // [1, n, 10] f32
    const float* W     = (const float*)d_in[1];   // [139, 128] f32
    float* out         = (float*)d_out;           // [1, n, n, 128] f32

    const int n = in_sizes[0] / 10;               // b == 1

    const int smem_bytes = TAB_ROWS * 128 * (int)sizeof(float) + n * (int)sizeof(int);
    cudaFuncSetAttribute(rpe_kernel, cudaFuncAttributeMaxDynamicSharedMemorySize, smem_bytes);

    rpe_kernel<<<n, 512, smem_bytes>>>(feats, W, out, n);
}